// round 13
// baseline (speedup 1.0000x reference)
#include <cuda_runtime.h>
#include <cuda_bf16.h>
#include <cstdint>

#define BB 2
#define QQ 300
#define TT 300
#define HH 256
#define WW 256
#define PP 12544
#define SPLITK 14
#define KC (PP / SPLITK)     // 896
#define KITERS (KC / 64)     // 14
#define NTILES 5             // ceil(300/64)

#define NTY 16               // row tiles per mask (16 rows each)
#define TROWS 16
#define PPT 49               // 256*49 = 12544
#define SROWT 257            // texels per tile row (xi = 0..256)

// ---------------- scratch ----------------
__device__ __nv_bfloat16 g_om[(size_t)BB * QQ * PP];
__device__ __nv_bfloat16 g_s [(size_t)BB * QQ * PP];
__device__ __nv_bfloat16 g_tm[(size_t)BB * TT * PP];
__device__ float g_negsum[BB * QQ];
__device__ float g_ssum [BB * QQ];
__device__ float g_tmsum [BB * TT];
__device__ float g_D1p[(size_t)SPLITK * BB * QQ * TT];
__device__ float g_D2p[(size_t)SPLITK * BB * QQ * TT];

__device__ float2 g_spt[(size_t)BB * PP];          // pre-scaled coords, sorted by tile
__device__ int g_binstart[BB][NTY + 1];
__device__ float g_psA[BB * 600 * NTY];
__device__ float g_psB[BB * 600 * NTY];

// ---------------- kernel 0: parallel counting sort; one CTA per (batch, bin), 16 bins (R9-proven) ----------------
__global__ __launch_bounds__(256) void bin_kernel(const float* __restrict__ point_coords)
{
    int b = blockIdx.x >> 4;
    int kbin = blockIdx.x & 15;
    int tid = threadIdx.x;
    int lane = tid & 31, warp = tid >> 5;
    const float2* pc = (const float2*)(point_coords + (size_t)b * PP * 2);

    __shared__ int hist[256 * NTY];
    __shared__ int total[NTY];
    __shared__ int s_base;

    int cnt[NTY];
    #pragma unroll
    for (int k = 0; k < NTY; k++) cnt[k] = 0;

    int start = tid * PPT;
    for (int j = 0; j < PPT; j++) {
        float2 pt = pc[start + j];
        float y = pt.y * (float)HH - 0.5f;
        int y0 = (int)floorf(y);
        int t = min(max(y0, 0), HH - 1) >> 4;
        cnt[t]++;
    }
    #pragma unroll
    for (int k = 0; k < NTY; k++) hist[tid * NTY + k] = cnt[k];
    __syncthreads();

    #pragma unroll
    for (int h = 0; h < 2; h++) {
        int bin = warp * 2 + h;
        int s = 0;
        #pragma unroll
        for (int i = 0; i < 8; i++) s += hist[(lane * 8 + i) * NTY + bin];
        #pragma unroll
        for (int o = 16; o > 0; o >>= 1) s += __shfl_down_sync(0xffffffffu, s, o);
        if (lane == 0) total[bin] = s;
    }
    __syncthreads();

    if (tid == 0) {
        int base = 0;
        for (int k = 0; k < kbin; k++) base += total[k];
        s_base = base;
        g_binstart[b][kbin] = base;
        if (kbin == NTY - 1) g_binstart[b][NTY] = PP;
    }

    if (warp == 0) {
        int v[8], pre[8], run = 0;
        #pragma unroll
        for (int i = 0; i < 8; i++) {
            v[i] = hist[(lane * 8 + i) * NTY + kbin];
            pre[i] = run; run += v[i];
        }
        int x = run;
        #pragma unroll
        for (int o = 1; o < 32; o <<= 1) {
            int y = __shfl_up_sync(0xffffffffu, x, o);
            if (lane >= o) x += y;
        }
        int excl = x - run;
        #pragma unroll
        for (int i = 0; i < 8; i++) hist[(lane * 8 + i) * NTY + kbin] = excl + pre[i];
    }
    __syncthreads();

    int off = s_base + hist[tid * NTY + kbin];
    for (int j = 0; j < PPT; j++) {
        float2 pt = pc[start + j];
        float x = pt.x * (float)WW - 0.5f;
        float y = pt.y * (float)HH - 0.5f;
        int y0 = (int)floorf(y);
        int t = min(max(y0, 0), HH - 1) >> 4;
        if (t == kbin) {
            g_spt[(size_t)b * PP + off] = make_float2(x, y);
            off++;
        }
    }
}

// ---------------- kernel 1: tiled sampling with pair-texel smem (2x LDS.64 per point) ----------------
// texel[row][xi] = (m[row][xi-1], m[row][xi]); one 64-bit gather yields both horizontal taps.
__global__ __launch_bounds__(256) void sample_kernel(
    const float* __restrict__ pred_masks,
    const float* __restrict__ tgt_masks)
{
    int bx = blockIdx.x;
    int tile = bx & (NTY - 1); bx >>= 4;
    int b = bx / 600;
    int r = bx % 600;
    bool is_pred = (r < 300);
    int m = is_pred ? r : r - 300;

    const float* mask = (is_pred ? pred_masks : tgt_masks) + ((size_t)(b * 300 + m)) * (HH * WW);
    size_t obase = (size_t)(b * 300 + m) * PP;

    __shared__ float2 sm2[17 * SROWT];   // 34.9 KB

    int tid = threadIdx.x;
    int row0 = tile * TROWS;
    int nrows = (tile == NTY - 1) ? TROWS : (TROWS + 1);

    // stage: for each mask element m[row][c], write texel[c].y and texel[c+1].x
    float* smf = (float*)sm2;
    for (int i = tid; i < nrows * WW; i += 256) {
        int row = i >> 8;
        int c = i & 255;
        float v = __ldg(mask + (size_t)(row0 + row) * WW + c);
        int base = (row * SROWT + c) * 2;   // float index of texel[row][c].x
        smf[base + 1] = v;                  // texel[c].y  = m[c]
        smf[base + 2] = v;                  // texel[c+1].x = m[c]
    }

    int pbeg = g_binstart[b][tile];
    int pend = g_binstart[b][tile + 1];
    __syncthreads();

    float s0 = 0.f, s1 = 0.f;
    const float2* spt = g_spt + (size_t)b * PP;

    for (int j = pbeg + tid; j < pend; j += 256) {
        float2 pt = spt[j];
        float x = pt.x, y = pt.y;
        float x0f = floorf(x), y0f = floorf(y);
        float wx = x - x0f, wy = y - y0f;
        int x0 = (int)x0f, y0 = (int)y0f;
        int xi = x0 + 1;                    // 0..256
        int ly0 = y0 - row0, ly1 = ly0 + 1;

        bool vx0 = (x0 >= 0);
        bool vx1 = (x0 + 1 <= WW - 1);
        bool vy0 = (y0 >= 0);
        bool vy1 = (y0 + 1 <= HH - 1);

        float2 z = make_float2(0.f, 0.f);
        float2 t0 = vy0 ? sm2[ly0 * SROWT + xi] : z;   // (m[y0][x0], m[y0][x1])
        float2 t1 = vy1 ? sm2[ly1 * SROWT + xi] : z;   // (m[y1][x0], m[y1][x1])

        float f00 = vx0 ? t0.x : 0.f;
        float f01 = vx1 ? t0.y : 0.f;
        float f10 = vx0 ? t1.x : 0.f;
        float f11 = vx1 ? t1.y : 0.f;

        float top = f00 + wx * (f01 - f00);
        float bot = f10 + wx * (f11 - f10);
        float om = top + wy * (bot - top);

        if (is_pred) {
            float sg = 1.f / (1.f + __expf(-om));
            float neg = fmaxf(om, 0.f) + log1pf(__expf(-fabsf(om)));  // softplus(om)
            g_om[obase + j] = __float2bfloat16(om);
            g_s [obase + j] = __float2bfloat16(sg);
            s0 += neg;
            s1 += sg;
        } else {
            g_tm[obase + j] = __float2bfloat16(om);
            s0 += om;
        }
    }

    #pragma unroll
    for (int o = 16; o > 0; o >>= 1) {
        s0 += __shfl_down_sync(0xffffffffu, s0, o);
        s1 += __shfl_down_sync(0xffffffffu, s1, o);
    }
    __shared__ float r0[8], r1[8];
    int lane = tid & 31, warp = tid >> 5;
    if (lane == 0) { r0[warp] = s0; r1[warp] = s1; }
    __syncthreads();
    if (tid == 0) {
        float t0 = 0.f, t1 = 0.f;
        #pragma unroll
        for (int i = 0; i < 8; i++) { t0 += r0[i]; t1 += r1[i]; }
        int idx = (b * 600 + r) * NTY + tile;
        g_psA[idx] = t0;
        g_psB[idx] = t1;
    }
}

// ---------------- kernel 1b ----------------
__global__ void reduce_sums_kernel()
{
    int idx = blockIdx.x * 256 + threadIdx.x;
    if (idx >= BB * 600) return;
    int b = idx / 600, r = idx % 600;
    float a = 0.f, c = 0.f;
    #pragma unroll
    for (int k = 0; k < NTY; k++) {
        a += g_psA[idx * NTY + k];
        c += g_psB[idx * NTY + k];
    }
    if (r < 300) {
        g_negsum[b * 300 + r] = a;
        g_ssum [b * 300 + r] = c;
    } else {
        g_tmsum[b * 300 + (r - 300)] = a;
    }
}

// ---------------- mma helpers ----------------
__device__ __forceinline__ void ldsm_x4_a(uint32_t* r, uint32_t a) {
    asm volatile("ldmatrix.sync.aligned.m8n8.x4.shared.b16 {%0,%1,%2,%3}, [%4];"
                 : "=r"(r[0]), "=r"(r[1]), "=r"(r[2]), "=r"(r[3]) : "r"(a));
}
__device__ __forceinline__ void mma16816(float* d, const uint32_t* a, const uint32_t* b) {
    asm volatile("mma.sync.aligned.m16n8k16.row.col.f32.bf16.bf16.f32 "
                 "{%0,%1,%2,%3}, {%4,%5,%6,%7}, {%8,%9}, {%0,%1,%2,%3};"
                 : "+f"(d[0]), "+f"(d[1]), "+f"(d[2]), "+f"(d[3])
                 : "r"(a[0]), "r"(a[1]), "r"(a[2]), "r"(a[3]), "r"(b[0]), "r"(b[1]));
}
__device__ __forceinline__ void cp16(uint32_t dst, const void* src, bool pred) {
    int sz = pred ? 16 : 0;
    asm volatile("cp.async.cg.shared.global [%0], [%1], 16, %2;"
                 :: "r"(dst), "l"(src), "r"(sz));
}
__device__ __forceinline__ uint32_t sw_off(int row, int col_e) {
    int chunk = col_e >> 3;
    return (uint32_t)(row * 128 + ((chunk ^ (row & 7)) << 4));
}

// ---------------- kernel 2: dual bf16 GEMM, 64x64 CTA tile, 4 warps, 32x32 warp tile (R10-proven) ----------------
__global__ __launch_bounds__(128) void gemm_kernel()
{
    int bx = blockIdx.x;
    int split = bx % SPLITK; bx /= SPLITK;
    int tt = bx % NTILES; bx /= NTILES;
    int qt = bx % NTILES;
    int b  = bx / NTILES;
    int m0 = qt * 64, n0 = tt * 64;

    __shared__ __align__(16) unsigned char smem[2][3][8192];
    uint32_t smem_base = (uint32_t)__cvta_generic_to_shared(&smem[0][0][0]);

    int tid = threadIdx.x;
    int warp = tid >> 5, lane = tid & 31;
    int wm0 = (warp >> 1) * 32;
    int wn0 = (warp & 1) * 32;

    float acc1[2][4][4];
    float acc2[2][4][4];
    #pragma unroll
    for (int i = 0; i < 2; i++)
        #pragma unroll
        for (int j = 0; j < 4; j++)
            #pragma unroll
            for (int k = 0; k < 4; k++) { acc1[i][j][k] = 0.f; acc2[i][j][k] = 0.f; }

    const __nv_bfloat16* Aom = g_om + (size_t)(b * 300) * PP;
    const __nv_bfloat16* As  = g_s  + (size_t)(b * 300) * PP;
    const __nv_bfloat16* Btm = g_tm + (size_t)(b * 300) * PP;

    int kbase = split * KC;

    auto load_stage = [&](int kt, int st) {
        int k0 = kbase + kt * 64;
        #pragma unroll
        for (int u = 0; u < 12; ++u) {
            int i = tid + u * 128;
            int a = i >> 9;
            int rem = i & 511;
            int row = rem >> 3;
            int ch = rem & 7;
            uint32_t dst = smem_base + (uint32_t)((st * 3 + a) * 8192) + sw_off(row, ch * 8);
            const __nv_bfloat16* srcbase = (a == 0) ? Aom : (a == 1) ? As : Btm;
            int g = ((a == 2) ? n0 : m0) + row;
            bool pred = (g < 300);
            const void* src = srcbase + (size_t)min(g, 299) * PP + k0 + ch * 8;
            cp16(dst, src, pred);
        }
        asm volatile("cp.async.commit_group;" ::: "memory");
    };

    load_stage(0, 0);

    for (int kt = 0; kt < KITERS; ++kt) {
        int st = kt & 1;
        if (kt + 1 < KITERS) {
            load_stage(kt + 1, (kt + 1) & 1);
            asm volatile("cp.async.wait_group 1;" ::: "memory");
        } else {
            asm volatile("cp.async.wait_group 0;" ::: "memory");
        }
        __syncthreads();

        uint32_t base_om = smem_base + (uint32_t)((st * 3 + 0) * 8192);
        uint32_t base_s  = smem_base + (uint32_t)((st * 3 + 1) * 8192);
        uint32_t base_tm = smem_base + (uint32_t)((st * 3 + 2) * 8192);

        #pragma unroll
        for (int ks = 0; ks < 4; ++ks) {
            uint32_t ao[2][4], av[2][4], bb[2][4];
            int arow = wm0 + (lane & 15);
            int acol = ks * 16 + (lane >> 4) * 8;
            #pragma unroll
            for (int ti = 0; ti < 2; ++ti) {
                ldsm_x4_a(ao[ti], base_om + sw_off(arow + ti * 16, acol));
                ldsm_x4_a(av[ti], base_s  + sw_off(arow + ti * 16, acol));
            }
            int mi = lane >> 3;
            int brow_base = wn0 + ((mi >> 1) * 8) + (lane & 7);
            int bcol = ks * 16 + (mi & 1) * 8;
            #pragma unroll
            for (int g2 = 0; g2 < 2; ++g2) {
                ldsm_x4_a(bb[g2], base_tm + sw_off(brow_base + g2 * 16, bcol));
            }
            #pragma unroll
            for (int ti = 0; ti < 2; ++ti)
                #pragma unroll
                for (int tn2 = 0; tn2 < 4; ++tn2) {
                    const uint32_t* bf = &bb[tn2 >> 1][(tn2 & 1) * 2];
                    mma16816(acc1[ti][tn2], ao[ti], bf);
                    mma16816(acc2[ti][tn2], av[ti], bf);
                }
        }
        __syncthreads();
    }

    float* D1 = g_D1p + ((size_t)(split * BB + b)) * (QQ * TT);
    float* D2 = g_D2p + ((size_t)(split * BB + b)) * (QQ * TT);
    #pragma unroll
    for (int ti = 0; ti < 2; ++ti)
        #pragma unroll
        for (int tn2 = 0; tn2 < 4; ++tn2)
            #pragma unroll
            for (int rh = 0; rh < 2; ++rh) {
                int q = m0 + wm0 + ti * 16 + (lane >> 2) + rh * 8;
                int t = n0 + wn0 + tn2 * 8 + (lane & 3) * 2;
                if (q < QQ && t < TT) {
                    float2 v1 = make_float2(acc1[ti][tn2][rh * 2 + 0], acc1[ti][tn2][rh * 2 + 1]);
                    float2 v2 = make_float2(acc2[ti][tn2][rh * 2 + 0], acc2[ti][tn2][rh * 2 + 1]);
                    *(float2*)&D1[q * TT + t] = v1;
                    *(float2*)&D2[q * TT + t] = v2;
                }
            }
}

// ---------------- kernel 3 ----------------
__global__ __launch_bounds__(256) void final_kernel(
    const float* __restrict__ pred_boxes,
    const float* __restrict__ tgt_boxes,
    float* __restrict__ out)
{
    int idx = blockIdx.x * 256 + threadIdx.x;
    if (idx >= BB * QQ * TT) return;
    int b = idx / (QQ * TT);
    int r = idx % (QQ * TT);
    int q = r / TT, t = r % TT;

    float D1 = 0.f, D2 = 0.f;
    #pragma unroll
    for (int s = 0; s < SPLITK; ++s) {
        size_t off = ((size_t)(s * BB + b)) * (QQ * TT) + r;
        D1 += g_D1p[off];
        D2 += g_D2p[off];
    }

    float ns = g_negsum[b * 300 + q];
    float ss = g_ssum [b * 300 + q];
    float ts = g_tmsum [b * 300 + t];

    float cost_mask = (ns - D1) * (1.f / (float)PP);
    float cost_dice = 1.f - (2.f * D2 + 1.f) / (ss + ts + 1.f);

    const float* pb = pred_boxes + (size_t)(b * 300 + q) * 4;
    const float* tb = tgt_boxes  + (size_t)(b * 300 + t) * 4;
    float p0 = pb[0], p1 = pb[1], p2 = pb[2], p3 = pb[3];
    float t0 = tb[0], t1 = tb[1], t2 = tb[2], t3 = tb[3];

    float cost_bbox = fabsf(p0 - t0) + fabsf(p1 - t1) + fabsf(p2 - t2) + fabsf(p3 - t3);

    float ax0 = p0 - 0.5f * p2, ay0 = p1 - 0.5f * p3;
    float ax1 = p0 + 0.5f * p2, ay1 = p1 + 0.5f * p3;
    float bx0 = t0 - 0.5f * t2, by0 = t1 - 0.5f * t3;
    float bx1 = t0 + 0.5f * t2, by1 = t1 + 0.5f * t3;

    float areaA = (ax1 - ax0) * (ay1 - ay0);
    float areaB = (bx1 - bx0) * (by1 - by0);
    float iw = fminf(ax1, bx1) - fmaxf(ax0, bx0);
    float ih = fminf(ay1, by1) - fmaxf(ay0, by0);
    iw = fmaxf(iw, 0.f); ih = fmaxf(ih, 0.f);
    float inter = iw * ih;
    float uni = areaA + areaB - inter;
    float iou = inter / uni;
    float ew = fmaxf(ax1, bx1) - fminf(ax0, bx0);
    float eh = fmaxf(ay1, by1) - fminf(ay0, by0);
    ew = fmaxf(ew, 0.f); eh = fmaxf(eh, 0.f);
    float ae = ew * eh;
    float giou = iou - (ae - uni) / ae;

    out[idx] = 5.f * cost_mask + 5.f * cost_dice + 5.f * cost_bbox - 2.f * giou;
}

// ---------------- launch ----------------
extern "C" void kernel_launch(void* const* d_in, const int* in_sizes, int n_in,
                              void* d_out, int out_size)
{
    const float* pred_masks   = (const float*)d_in[0];
    const float* tgt_masks    = (const float*)d_in[1];
    const float* pred_boxes   = (const float*)d_in[2];
    const float* tgt_boxes    = (const float*)d_in[3];
    const float* point_coords = (const float*)d_in[4];
    float* out = (float*)d_out;

    bin_kernel<<<BB * NTY, 256>>>(point_coords);
    sample_kernel<<<BB * 600 * NTY, 256>>>(pred_masks, tgt_masks);
    reduce_sums_kernel<<<(BB * 600 + 255) / 256, 256>>>();
    gemm_kernel<<<BB * NTILES * NTILES * SPLITK, 128>>>();
    final_kernel<<<(BB * QQ * TT + 255) / 256, 256>>>(pred_boxes, tgt_boxes, out);
}

// round 16
// speedup vs baseline: 1.2505x; 1.2505x over previous
#include <cuda_runtime.h>
#include <cuda_bf16.h>
#include <cstdint>

#define BB 2
#define QQ 300
#define TT 300
#define HH 256
#define WW 256
#define PP 12544
#define SPLITK 14
#define KC (PP / SPLITK)     // 896
#define KITERS (KC / 64)     // 14
#define NTILES 5             // ceil(300/64)

#define NTY 8                // row tiles per mask
#define TROWS 32
#define PPT 49               // 256*49 = 12544

// ---------------- scratch ----------------
__device__ __nv_bfloat16 g_om[(size_t)BB * QQ * PP];
__device__ __nv_bfloat16 g_s [(size_t)BB * QQ * PP];
__device__ __nv_bfloat16 g_tm[(size_t)BB * TT * PP];
__device__ float g_negsum[BB * QQ];
__device__ float g_ssum [BB * QQ];
__device__ float g_tmsum [BB * TT];
__device__ float g_D1p[(size_t)SPLITK * BB * QQ * TT];
__device__ float g_D2p[(size_t)SPLITK * BB * QQ * TT];

__device__ float2 g_spt[(size_t)BB * PP];          // pre-scaled coords, sorted by tile
__device__ int g_binstart[BB][NTY + 1];
__device__ float g_psA[BB * 600 * NTY];
__device__ float g_psB[BB * 600 * NTY];

// ---------------- kernel 0: parallel counting sort; one CTA per (batch, bin) (R8-proven) ----------------
__global__ __launch_bounds__(256) void bin_kernel(const float* __restrict__ point_coords)
{
    int b = blockIdx.x >> 3;
    int kbin = blockIdx.x & 7;
    int tid = threadIdx.x;
    int lane = tid & 31, warp = tid >> 5;
    const float2* pc = (const float2*)(point_coords + (size_t)b * PP * 2);

    __shared__ int hist[256 * NTY];
    __shared__ int total[NTY];
    __shared__ int s_base;

    int cnt[NTY];
    #pragma unroll
    for (int k = 0; k < NTY; k++) cnt[k] = 0;

    int start = tid * PPT;
    for (int j = 0; j < PPT; j++) {
        float2 pt = pc[start + j];
        float y = pt.y * (float)HH - 0.5f;
        int y0 = (int)floorf(y);
        int t = min(max(y0, 0), HH - 1) >> 5;
        cnt[t]++;
    }
    #pragma unroll
    for (int k = 0; k < NTY; k++) hist[tid * NTY + k] = cnt[k];
    __syncthreads();

    {
        int s = 0;
        #pragma unroll
        for (int i = 0; i < 8; i++) s += hist[(lane * 8 + i) * NTY + warp];
        #pragma unroll
        for (int o = 16; o > 0; o >>= 1) s += __shfl_down_sync(0xffffffffu, s, o);
        if (lane == 0) total[warp] = s;
    }
    __syncthreads();

    if (tid == 0) {
        int base = 0;
        for (int k = 0; k < kbin; k++) base += total[k];
        s_base = base;
        g_binstart[b][kbin] = base;
        if (kbin == NTY - 1) g_binstart[b][NTY] = PP;
    }

    if (warp == 0) {
        int v[8], pre[8], run = 0;
        #pragma unroll
        for (int i = 0; i < 8; i++) {
            v[i] = hist[(lane * 8 + i) * NTY + kbin];
            pre[i] = run; run += v[i];
        }
        int x = run;
        #pragma unroll
        for (int o = 1; o < 32; o <<= 1) {
            int y = __shfl_up_sync(0xffffffffu, x, o);
            if (lane >= o) x += y;
        }
        int excl = x - run;
        #pragma unroll
        for (int i = 0; i < 8; i++) hist[(lane * 8 + i) * NTY + kbin] = excl + pre[i];
    }
    __syncthreads();

    int off = s_base + hist[tid * NTY + kbin];
    for (int j = 0; j < PPT; j++) {
        float2 pt = pc[start + j];
        float x = pt.x * (float)WW - 0.5f;
        float y = pt.y * (float)HH - 0.5f;
        int y0 = (int)floorf(y);
        int t = min(max(y0, 0), HH - 1) >> 5;
        if (t == kbin) {
            g_spt[(size_t)b * PP + off] = make_float2(x, y);
            off++;
        }
    }
}

// ---------------- kernel 1: tiled sampling, coalesced stores (R4/R10-proven; FROZEN) ----------------
__global__ __launch_bounds__(256) void sample_kernel(
    const float* __restrict__ pred_masks,
    const float* __restrict__ tgt_masks)
{
    int bx = blockIdx.x;
    int tile = bx & (NTY - 1); bx >>= 3;
    int b = bx / 600;
    int r = bx % 600;
    bool is_pred = (r < 300);
    int m = is_pred ? r : r - 300;

    const float* mask = (is_pred ? pred_masks : tgt_masks) + ((size_t)(b * 300 + m)) * (HH * WW);
    size_t obase = (size_t)(b * 300 + m) * PP;

    __shared__ float sm[33 * WW];

    int row0 = tile * TROWS;
    int nrows = (tile == NTY - 1) ? TROWS : (TROWS + 1);

    int nvec = nrows * (WW / 4);
    for (int i = threadIdx.x; i < nvec; i += 256) {
        int row = i >> 6;
        int c = (i & 63) * 4;
        float4 v = __ldg((const float4*)(mask + (size_t)(row0 + row) * WW + c));
        *(float4*)&sm[row * WW + c] = v;
    }

    int pbeg = g_binstart[b][tile];
    int pend = g_binstart[b][tile + 1];
    __syncthreads();

    float s0 = 0.f, s1 = 0.f;
    const float2* spt = g_spt + (size_t)b * PP;

    for (int j = pbeg + threadIdx.x; j < pend; j += 256) {
        float2 pt = spt[j];
        float x = pt.x, y = pt.y;
        float x0f = floorf(x), y0f = floorf(y);
        float wx = x - x0f, wy = y - y0f;
        int x0 = (int)x0f, y0 = (int)y0f;
        int x1 = x0 + 1, y1 = y0 + 1;
        int ly0 = y0 - row0, ly1 = ly0 + 1;

        bool vx0 = (x0 >= 0);
        bool vx1 = (x1 <= WW - 1);
        bool vy0 = (y0 >= 0);
        bool vy1 = (y1 <= HH - 1);

        float f00 = (vy0 && vx0) ? sm[ly0 * WW + x0] : 0.f;
        float f01 = (vy0 && vx1) ? sm[ly0 * WW + x1] : 0.f;
        float f10 = (vy1 && vx0) ? sm[ly1 * WW + x0] : 0.f;
        float f11 = (vy1 && vx1) ? sm[ly1 * WW + x1] : 0.f;

        float om = f00 * (1.f - wy) * (1.f - wx) + f01 * (1.f - wy) * wx +
                   f10 * wy * (1.f - wx) + f11 * wy * wx;

        if (is_pred) {
            float sg = 1.f / (1.f + __expf(-om));
            float neg = fmaxf(om, 0.f) + log1pf(__expf(-fabsf(om)));  // softplus(om)
            g_om[obase + j] = __float2bfloat16(om);
            g_s [obase + j] = __float2bfloat16(sg);
            s0 += neg;
            s1 += sg;
        } else {
            g_tm[obase + j] = __float2bfloat16(om);
            s0 += om;
        }
    }

    #pragma unroll
    for (int o = 16; o > 0; o >>= 1) {
        s0 += __shfl_down_sync(0xffffffffu, s0, o);
        s1 += __shfl_down_sync(0xffffffffu, s1, o);
    }
    __shared__ float r0[8], r1[8];
    int lane = threadIdx.x & 31, warp = threadIdx.x >> 5;
    if (lane == 0) { r0[warp] = s0; r1[warp] = s1; }
    __syncthreads();
    if (threadIdx.x == 0) {
        float t0 = 0.f, t1 = 0.f;
        #pragma unroll
        for (int i = 0; i < 8; i++) { t0 += r0[i]; t1 += r1[i]; }
        int idx = (b * 600 + r) * NTY + tile;
        g_psA[idx] = t0;
        g_psB[idx] = t1;
    }
}

// ---------------- kernel 1b ----------------
__global__ void reduce_sums_kernel()
{
    int idx = blockIdx.x * 256 + threadIdx.x;
    if (idx >= BB * 600) return;
    int b = idx / 600, r = idx % 600;
    float a = 0.f, c = 0.f;
    #pragma unroll
    for (int k = 0; k < NTY; k++) {
        a += g_psA[idx * NTY + k];
        c += g_psB[idx * NTY + k];
    }
    if (r < 300) {
        g_negsum[b * 300 + r] = a;
        g_ssum [b * 300 + r] = c;
    } else {
        g_tmsum[b * 300 + (r - 300)] = a;
    }
}

// ---------------- mma helpers ----------------
__device__ __forceinline__ void ldsm_x4_a(uint32_t* r, uint32_t a) {
    asm volatile("ldmatrix.sync.aligned.m8n8.x4.shared.b16 {%0,%1,%2,%3}, [%4];"
                 : "=r"(r[0]), "=r"(r[1]), "=r"(r[2]), "=r"(r[3]) : "r"(a));
}
__device__ __forceinline__ void mma16816(float* d, const uint32_t* a, const uint32_t* b) {
    asm volatile("mma.sync.aligned.m16n8k16.row.col.f32.bf16.bf16.f32 "
                 "{%0,%1,%2,%3}, {%4,%5,%6,%7}, {%8,%9}, {%0,%1,%2,%3};"
                 : "+f"(d[0]), "+f"(d[1]), "+f"(d[2]), "+f"(d[3])
                 : "r"(a[0]), "r"(a[1]), "r"(a[2]), "r"(a[3]), "r"(b[0]), "r"(b[1]));
}
__device__ __forceinline__ void cp16(uint32_t dst, const void* src, bool pred) {
    int sz = pred ? 16 : 0;
    asm volatile("cp.async.cg.shared.global [%0], [%1], 16, %2;"
                 :: "r"(dst), "l"(src), "r"(sz));
}
__device__ __forceinline__ uint32_t sw_off(int row, int col_e) {
    int chunk = col_e >> 3;
    return (uint32_t)(row * 128 + ((chunk ^ (row & 7)) << 4));
}

// ---------------- kernel 2: dual bf16 GEMM, 64x64 CTA tile, 4 warps, 32x32 warp tile ----------------
// R10 mainloop with the barrier schedule reduced to ONE __syncthreads per k-iter:
//   wait_group 0  -> stage kt complete (this thread's groups all drained)
//   __syncthreads -> publishes stage kt CTA-wide AND separates compute(kt-1)
//                    from the overwrite of stage (kt+1)&1 == (kt-1)&1
//   issue load(kt+1), then compute(kt) overlapped with the async load.
__global__ __launch_bounds__(128) void gemm_kernel()
{
    int bx = blockIdx.x;
    int split = bx % SPLITK; bx /= SPLITK;
    int tt = bx % NTILES; bx /= NTILES;
    int qt = bx % NTILES;
    int b  = bx / NTILES;
    int m0 = qt * 64, n0 = tt * 64;

    __shared__ __align__(16) unsigned char smem[2][3][8192];
    uint32_t smem_base = (uint32_t)__cvta_generic_to_shared(&smem[0][0][0]);

    int tid = threadIdx.x;
    int warp = tid >> 5, lane = tid & 31;
    int wm0 = (warp >> 1) * 32;
    int wn0 = (warp & 1) * 32;

    float acc1[2][4][4];
    float acc2[2][4][4];
    #pragma unroll
    for (int i = 0; i < 2; i++)
        #pragma unroll
        for (int j = 0; j < 4; j++)
            #pragma unroll
            for (int k = 0; k < 4; k++) { acc1[i][j][k] = 0.f; acc2[i][j][k] = 0.f; }

    const __nv_bfloat16* Aom = g_om + (size_t)(b * 300) * PP;
    const __nv_bfloat16* As  = g_s  + (size_t)(b * 300) * PP;
    const __nv_bfloat16* Btm = g_tm + (size_t)(b * 300) * PP;

    int kbase = split * KC;

    auto load_stage = [&](int kt, int st) {
        int k0 = kbase + kt * 64;
        #pragma unroll
        for (int u = 0; u < 12; ++u) {
            int i = tid + u * 128;
            int a = i >> 9;
            int rem = i & 511;
            int row = rem >> 3;
            int ch = rem & 7;
            uint32_t dst = smem_base + (uint32_t)((st * 3 + a) * 8192) + sw_off(row, ch * 8);
            const __nv_bfloat16* srcbase = (a == 0) ? Aom : (a == 1) ? As : Btm;
            int g = ((a == 2) ? n0 : m0) + row;
            bool pred = (g < 300);
            const void* src = srcbase + (size_t)min(g, 299) * PP + k0 + ch * 8;
            cp16(dst, src, pred);
        }
        asm volatile("cp.async.commit_group;" ::: "memory");
    };

    load_stage(0, 0);

    for (int kt = 0; kt < KITERS; ++kt) {
        int st = kt & 1;
        // stage kt ready (per-thread), then publish CTA-wide; this same barrier
        // orders compute(kt-1) before the overwrite of its buffer below.
        asm volatile("cp.async.wait_group 0;" ::: "memory");
        __syncthreads();
        if (kt + 1 < KITERS) load_stage(kt + 1, (kt + 1) & 1);

        uint32_t base_om = smem_base + (uint32_t)((st * 3 + 0) * 8192);
        uint32_t base_s  = smem_base + (uint32_t)((st * 3 + 1) * 8192);
        uint32_t base_tm = smem_base + (uint32_t)((st * 3 + 2) * 8192);

        #pragma unroll
        for (int ks = 0; ks < 4; ++ks) {
            uint32_t ao[2][4], av[2][4], bb[2][4];
            int arow = wm0 + (lane & 15);
            int acol = ks * 16 + (lane >> 4) * 8;
            #pragma unroll
            for (int ti = 0; ti < 2; ++ti) {
                ldsm_x4_a(ao[ti], base_om + sw_off(arow + ti * 16, acol));
                ldsm_x4_a(av[ti], base_s  + sw_off(arow + ti * 16, acol));
            }
            int mi = lane >> 3;
            int brow_base = wn0 + ((mi >> 1) * 8) + (lane & 7);
            int bcol = ks * 16 + (mi & 1) * 8;
            #pragma unroll
            for (int g2 = 0; g2 < 2; ++g2) {
                ldsm_x4_a(bb[g2], base_tm + sw_off(brow_base + g2 * 16, bcol));
            }
            #pragma unroll
            for (int ti = 0; ti < 2; ++ti)
                #pragma unroll
                for (int tn2 = 0; tn2 < 4; ++tn2) {
                    const uint32_t* bf = &bb[tn2 >> 1][(tn2 & 1) * 2];
                    mma16816(acc1[ti][tn2], ao[ti], bf);
                    mma16816(acc2[ti][tn2], av[ti], bf);
                }
        }
    }

    float* D1 = g_D1p + ((size_t)(split * BB + b)) * (QQ * TT);
    float* D2 = g_D2p + ((size_t)(split * BB + b)) * (QQ * TT);
    #pragma unroll
    for (int ti = 0; ti < 2; ++ti)
        #pragma unroll
        for (int tn2 = 0; tn2 < 4; ++tn2)
            #pragma unroll
            for (int rh = 0; rh < 2; ++rh) {
                int q = m0 + wm0 + ti * 16 + (lane >> 2) + rh * 8;
                int t = n0 + wn0 + tn2 * 8 + (lane & 3) * 2;
                if (q < QQ && t < TT) {
                    float2 v1 = make_float2(acc1[ti][tn2][rh * 2 + 0], acc1[ti][tn2][rh * 2 + 1]);
                    float2 v2 = make_float2(acc2[ti][tn2][rh * 2 + 0], acc2[ti][tn2][rh * 2 + 1]);
                    *(float2*)&D1[q * TT + t] = v1;
                    *(float2*)&D2[q * TT + t] = v2;
                }
            }
}

// ---------------- kernel 3 ----------------
__global__ __launch_bounds__(256) void final_kernel(
    const float* __restrict__ pred_boxes,
    const float* __restrict__ tgt_boxes,
    float* __restrict__ out)
{
    int idx = blockIdx.x * 256 + threadIdx.x;
    if (idx >= BB * QQ * TT) return;
    int b = idx / (QQ * TT);
    int r = idx % (QQ * TT);
    int q = r / TT, t = r % TT;

    float D1 = 0.f, D2 = 0.f;
    #pragma unroll
    for (int s = 0; s < SPLITK; ++s) {
        size_t off = ((size_t)(s * BB + b)) * (QQ * TT) + r;
        D1 += g_D1p[off];
        D2 += g_D2p[off];
    }

    float ns = g_negsum[b * 300 + q];
    float ss = g_ssum [b * 300 + q];
    float ts = g_tmsum [b * 300 + t];

    float cost_mask = (ns - D1) * (1.f / (float)PP);
    float cost_dice = 1.f - (2.f * D2 + 1.f) / (ss + ts + 1.f);

    const float* pb = pred_boxes + (size_t)(b * 300 + q) * 4;
    const float* tb = tgt_boxes  + (size_t)(b * 300 + t) * 4;
    float p0 = pb[0], p1 = pb[1], p2 = pb[2], p3 = pb[3];
    float t0 = tb[0], t1 = tb[1], t2 = tb[2], t3 = tb[3];

    float cost_bbox = fabsf(p0 - t0) + fabsf(p1 - t1) + fabsf(p2 - t2) + fabsf(p3 - t3);

    float ax0 = p0 - 0.5f * p2, ay0 = p1 - 0.5f * p3;
    float ax1 = p0 + 0.5f * p2, ay1 = p1 + 0.5f * p3;
    float bx0 = t0 - 0.5f * t2, by0 = t1 - 0.5f * t3;
    float bx1 = t0 + 0.5f * t2, by1 = t1 + 0.5f * t3;

    float areaA = (ax1 - ax0) * (ay1 - ay0);
    float areaB = (bx1 - bx0) * (by1 - by0);
    float iw = fminf(ax1, bx1) - fmaxf(ax0, bx0);
    float ih = fminf(ay1, by1) - fmaxf(ay0, by0);
    iw = fmaxf(iw, 0.f); ih = fmaxf(ih, 0.f);
    float inter = iw * ih;
    float uni = areaA + areaB - inter;
    float iou = inter / uni;
    float ew = fmaxf(ax1, bx1) - fminf(ax0, bx0);
    float eh = fmaxf(ay1, by1) - fminf(ay0, by0);
    ew = fmaxf(ew, 0.f); eh = fmaxf(eh, 0.f);
    float ae = ew * eh;
    float giou = iou - (ae - uni) / ae;

    out[idx] = 5.f * cost_mask + 5.f * cost_dice + 5.f * cost_bbox - 2.f * giou;
}

// ---------------- launch ----------------
extern "C" void kernel_launch(void* const* d_in, const int* in_sizes, int n_in,
                              void* d_out, int out_size)
{
    const float* pred_masks   = (const float*)d_in[0];
    const float* tgt_masks    = (const float*)d_in[1];
    const float* pred_boxes   = (const float*)d_in[2];
    const float* tgt_boxes    = (const float*)d_in[3];
    const float* point_coords = (const float*)d_in[4];
    float* out = (float*)d_out;

    bin_kernel<<<BB * NTY, 256>>>(point_coords);
    sample_kernel<<<BB * 600 * NTY, 256>>>(pred_masks, tgt_masks);
    reduce_sums_kernel<<<(BB * 600 + 255) / 256, 256>>>();
    gemm_kernel<<<BB * NTILES * NTILES * SPLITK, 128>>>();
    final_kernel<<<(BB * QQ * TT + 255) / 256, 256>>>(pred_boxes, tgt_boxes, out);
}